// round 1
// baseline (speedup 1.0000x reference)
#include <cuda_runtime.h>
#include <math.h>
#include <stdint.h>

// Problem: FootAndBall ball-detection post-process.
//  in : [16, 2, 540, 960] fp32 logits
//  out: [16, 100, 5] fp32 detections (x1,y1,x2,y2,score), sorted desc by score.

#define BB   16
#define HH   540
#define WW   960
#define HWSZ (HH * WW)
#define KK   100
#define NBINS 65536          // bin = float_bits >> 14 ; p in (0,1) so bin <= 65023
#define MAXC  262144         // per-batch candidate capacity (expected ~57.6k)

__device__ int   g_cnt[BB];
__device__ int   g_hist[BB][NBINS];
__device__ float g_cval[BB][MAXC];
__device__ int   g_cidx[BB][MAXC];

// ---------------------------------------------------------------------------
// Kernel 0: zero per-launch state (graph replays must be deterministic)
// ---------------------------------------------------------------------------
__global__ void zero_kernel() {
    int i = blockIdx.x * blockDim.x + threadIdx.x;
    if (i < BB * NBINS) ((int*)g_hist)[i] = 0;
    if (i < BB) g_cnt[i] = 0;
}

// ---------------------------------------------------------------------------
// softmax channel-1 prob as an exact function of d = fl(x1 - x0).
// Matches jax.nn.softmax numerics: m = max(x0,x1); p = e^(x1-m)/(e^(x0-m)+e^(x1-m)).
// One exponent arg is exactly 0 (exp -> 1.0f), and fl(x0-x1) == -d exactly.
// ---------------------------------------------------------------------------
__device__ __forceinline__ float prob_from_d(float d) {
#ifdef __FAST_MATH__
    // -use_fast_math would degrade expf; use double path (correctly rounded).
    double dd = (double)d;
    double p = (d >= 0.0f) ? (1.0 / (exp(-dd) + 1.0))
                           : (exp(dd) / (exp(dd) + 1.0));
    return (float)p;
#else
    if (d >= 0.0f) {
        float e0 = expf(-d);           // e^(x0 - x1), e1 = 1
        return 1.0f / (e0 + 1.0f);
    } else {
        float e1 = expf(d);            // e^(x1 - x0), e0 = 1
        return e1 / (1.0f + e1);
    }
#endif
}

// ---------------------------------------------------------------------------
// Kernel 1: fused d-map + 3x3 NMS + candidate emit + histogram.
// Tile 128x8 per 256-thread block, halo in shared memory.
// ---------------------------------------------------------------------------
#define TILE_W 128
#define TILE_H 8

__global__ __launch_bounds__(256) void detect_kernel(const float* __restrict__ in) {
    __shared__ float sd[TILE_H + 2][TILE_W + 4];   // 10 x 132 (pad vs bank conflicts)

    const int b   = blockIdx.z;
    const int bx0 = blockIdx.x * TILE_W;
    const int by0 = blockIdx.y * TILE_H;
    const float* __restrict__ p0 = in + (size_t)b * 2 * HWSZ;
    const float* __restrict__ p1 = p0 + HWSZ;

    const int lane = threadIdx.x;        // 0..31
    const int ty   = threadIdx.y;        // 0..7 (== warp id)
    const int tid  = ty * 32 + lane;

    // Load (TILE_H+2) x (TILE_W+2) halo of d = x1 - x0; OOB = -inf (SAME pad).
    for (int i = tid; i < (TILE_H + 2) * (TILE_W + 2); i += 256) {
        int r  = i / (TILE_W + 2);
        int c  = i % (TILE_W + 2);
        int gx = bx0 + c - 1;
        int gy = by0 + r - 1;
        float d = -INFINITY;
        if (gx >= 0 && gx < WW && gy >= 0 && gy < HH) {
            int o = gy * WW + gx;
            d = p1[o] - p0[o];
        }
        sd[r][c] = d;
    }
    __syncthreads();

    const int gy = by0 + ty;

    #pragma unroll
    for (int k = 0; k < 4; k++) {
        const int cx = lane + k * 32;
        const int gx = bx0 + cx;

        const float d = sd[ty + 1][cx + 1];
        float m = fmaxf(fmaxf(sd[ty][cx],     sd[ty][cx + 1]),     sd[ty][cx + 2]);
        m = fmaxf(m, fmaxf(sd[ty + 1][cx],                          sd[ty + 1][cx + 2]));
        m = fmaxf(m, fmaxf(fmaxf(sd[ty + 2][cx], sd[ty + 2][cx + 1]), sd[ty + 2][cx + 2]));

        const bool cand = (gx < WW) && (gy < HH) && (d >= m);   // d == 3x3 max

        // Warp-aggregated candidate append.
        unsigned mask = __ballot_sync(0xffffffffu, cand);
        if (mask) {
            int nc     = __popc(mask);
            int leader = __ffs(mask) - 1;
            int base   = 0;
            if (lane == leader) base = atomicAdd(&g_cnt[b], nc);
            base = __shfl_sync(0xffffffffu, base, leader);
            if (cand) {
                int pos = base + __popc(mask & ((1u << lane) - 1u));
                if (pos < MAXC) {
                    float p = prob_from_d(d);
                    g_cval[b][pos] = p;
                    g_cidx[b][pos] = gy * WW + gx;
                    atomicAdd(&g_hist[b][__float_as_uint(p) >> 14], 1);
                }
            }
        }
    }
}

// ---------------------------------------------------------------------------
// Kernel 2: per-batch threshold (histogram suffix scan) + collect + exact
// stable rank of survivors + output write. One block per batch.
// ---------------------------------------------------------------------------
#define COLLECT_CAP 1024

__global__ __launch_bounds__(256) void select_kernel(float* __restrict__ out) {
    __shared__ int   s_psum[256];
    __shared__ int   s_seg, s_above, s_cutbits, s_count;
    __shared__ float s_val[COLLECT_CAP];
    __shared__ int   s_idx[COLLECT_CAP];

    const int b = blockIdx.x;
    const int t = threadIdx.x;
    const int* __restrict__ hb = g_hist[b];

    // Coarse pass: per-thread sums over 256 contiguous bins.
    int acc = 0;
    #pragma unroll 8
    for (int j = 0; j < 256; j++) acc += hb[t * 256 + j];
    s_psum[t] = acc;
    if (t == 0) s_count = 0;
    __syncthreads();

    if (t == 0) {
        int above = 0, seg = 0;
        for (int s = 255; s >= 0; s--) {
            if (above + s_psum[s] >= KK) { seg = s; break; }
            above += s_psum[s];
        }
        s_seg = seg; s_above = above;
    }
    __syncthreads();

    // Fine pass within the cut segment.
    const int seg = s_seg;
    s_psum[t] = hb[seg * 256 + t];
    __syncthreads();
    if (t == 0) {
        int above = s_above;
        int cut = seg * 256;
        for (int c = 255; c >= 0; c--) {
            if (above + s_psum[c] >= KK) { cut = seg * 256 + c; break; }
            above += s_psum[c];
        }
        s_cutbits = cut << 14;
    }
    __syncthreads();

    // Collect all candidates with bits >= cutbits (count in [100, ~100+binpop]).
    const unsigned cutbits = (unsigned)s_cutbits;
    const int n = min(g_cnt[b], MAXC);
    for (int i = t; i < n; i += 256) {
        float v = g_cval[b][i];
        if (__float_as_uint(v) >= cutbits) {
            int pos = atomicAdd(&s_count, 1);
            if (pos < COLLECT_CAP) { s_val[pos] = v; s_idx[pos] = g_cidx[b][i]; }
        }
    }
    __syncthreads();

    // Exact stable rank: value desc, index asc (matches lax.top_k tie-break).
    const int C = min(s_count, COLLECT_CAP);
    for (int e = t; e < C; e += 256) {
        const float v  = s_val[e];
        const int   id = s_idx[e];
        int rank = 0;
        for (int j = 0; j < C; j++) {
            float vj = s_val[j];
            rank += (vj > v) || (vj == v && s_idx[j] < id);
        }
        if (rank < KK) {
            int w = id % WW;
            int h = id / WW;
            float xc = (float)w * 4.0f + 1.5f;
            float yc = (float)h * 4.0f + 1.5f;
            float* o = out + ((size_t)b * KK + rank) * 5;
            o[0] = xc - 10.0f;
            o[1] = yc - 10.0f;
            o[2] = xc + 10.0f;
            o[3] = yc + 10.0f;
            o[4] = v;
        }
    }
}

// ---------------------------------------------------------------------------
extern "C" void kernel_launch(void* const* d_in, const int* in_sizes, int n_in,
                              void* d_out, int out_size) {
    const float* in = (const float*)d_in[0];
    float* out = (float*)d_out;

    // 0) reset counters + histogram
    {
        int total = BB * NBINS;
        zero_kernel<<<(total + 255) / 256, 256>>>();
    }

    // 1) fused softmax-equivalent + NMS + candidate emit
    {
        dim3 block(32, 8);
        dim3 grid((WW + TILE_W - 1) / TILE_W, (HH + TILE_H - 1) / TILE_H, BB);
        detect_kernel<<<grid, block>>>(in);
    }

    // 2) per-batch top-100 + box write
    select_kernel<<<BB, 256>>>(out);
}

// round 2
// speedup vs baseline: 1.6331x; 1.6331x over previous
#include <cuda_runtime.h>
#include <math.h>
#include <stdint.h>

// Problem: FootAndBall ball-detection post-process.
//  in : [16, 2, 540, 960] fp32 logits
//  out: [16, 100, 5] fp32 detections (x1,y1,x2,y2,score), sorted desc by score.

#define BB   16
#define HH   540
#define WW   960
#define HWSZ (HH * WW)
#define KK   100
#define NBINS 65536          // bin = float_bits >> 14 ; p in (0,1) so bin <= 65023
#define MAXC  262144         // per-batch candidate capacity (expected ~57.6k)

__device__ int   g_cnt[BB];
__device__ int   g_hist[BB][NBINS];
__device__ float g_cval[BB][MAXC];
__device__ int   g_cidx[BB][MAXC];

// ---------------------------------------------------------------------------
// Kernel 0: zero per-launch state (graph replays must be deterministic)
// 4MB hist + cnt, vectorized int4 stores.
// ---------------------------------------------------------------------------
__global__ void zero_kernel() {
    int i = blockIdx.x * blockDim.x + threadIdx.x;
    int4* h4 = (int4*)g_hist;
    const int n4 = (BB * NBINS) / 4;
    if (i < n4) h4[i] = make_int4(0, 0, 0, 0);
    if (i < BB) g_cnt[i] = 0;
}

// ---------------------------------------------------------------------------
// softmax channel-1 prob as an exact function of d = fl(x1 - x0).
// Matches jax.nn.softmax numerics: m = max(x0,x1); p = e^(x1-m)/(e^(x0-m)+e^(x1-m)).
// One exponent arg is exactly 0 (exp -> 1.0f), and fl(x0-x1) == -d exactly.
// ---------------------------------------------------------------------------
__device__ __forceinline__ float prob_from_d(float d) {
#ifdef __FAST_MATH__
    double dd = (double)d;
    double p = (d >= 0.0f) ? (1.0 / (exp(-dd) + 1.0))
                           : (exp(dd) / (exp(dd) + 1.0));
    return (float)p;
#else
    if (d >= 0.0f) {
        float e0 = expf(-d);           // e^(x0 - x1), e1 = 1
        return 1.0f / (e0 + 1.0f);
    } else {
        float e1 = expf(d);            // e^(x1 - x0), e0 = 1
        return e1 / (1.0f + e1);
    }
#endif
}

// ---------------------------------------------------------------------------
// Kernel 1: fused d-map + 3x3 NMS + candidate emit + histogram.
// Tile 128x8 per 256-thread block, halo in shared memory.
// Candidate slots reserved with ONE global atomic per block (block-level
// aggregation) — the per-warp global atomic in R1 serialized on 16 addresses
// and cost ~230us.
// ---------------------------------------------------------------------------
#define TILE_W 128
#define TILE_H 8

__global__ __launch_bounds__(256) void detect_kernel(const float* __restrict__ in) {
    __shared__ float sd[TILE_H + 2][TILE_W + 4];   // 10 x 132 (pad vs bank conflicts)
    __shared__ int   s_off[32];                    // per (warp, k) exclusive offsets
    __shared__ int   s_base;

    const int b   = blockIdx.z;
    const int bx0 = blockIdx.x * TILE_W;
    const int by0 = blockIdx.y * TILE_H;
    const float* __restrict__ p0 = in + (size_t)b * 2 * HWSZ;
    const float* __restrict__ p1 = p0 + HWSZ;

    const int lane = threadIdx.x;        // 0..31
    const int ty   = threadIdx.y;        // 0..7 (== warp id)
    const int tid  = ty * 32 + lane;

    // Load (TILE_H+2) x (TILE_W+2) halo of d = x1 - x0; OOB = -inf (SAME pad).
    for (int i = tid; i < (TILE_H + 2) * (TILE_W + 2); i += 256) {
        int r  = i / (TILE_W + 2);
        int c  = i % (TILE_W + 2);
        int gx = bx0 + c - 1;
        int gy = by0 + r - 1;
        float d = -INFINITY;
        if (gx >= 0 && gx < WW && gy >= 0 && gy < HH) {
            int o = gy * WW + gx;
            d = p1[o] - p0[o];
        }
        sd[r][c] = d;
    }
    __syncthreads();

    const int gy = by0 + ty;

    // ---- Phase 1: NMS decision, per-warp ballots (no global atomics) ----
    float    dv[4];
    unsigned um[4];
    #pragma unroll
    for (int k = 0; k < 4; k++) {
        const int cx = lane + k * 32;
        const int gx = bx0 + cx;

        const float d = sd[ty + 1][cx + 1];
        float m = fmaxf(fmaxf(sd[ty][cx],     sd[ty][cx + 1]),     sd[ty][cx + 2]);
        m = fmaxf(m, fmaxf(sd[ty + 1][cx],                          sd[ty + 1][cx + 2]));
        m = fmaxf(m, fmaxf(fmaxf(sd[ty + 2][cx], sd[ty + 2][cx + 1]), sd[ty + 2][cx + 2]));

        const bool cand = (gx < WW) && (gy < HH) && (d >= m);   // d == 3x3 max
        um[k] = __ballot_sync(0xffffffffu, cand);
        dv[k] = d;
    }
    if (lane < 4) s_off[ty * 4 + lane] = __popc(um[lane]);
    __syncthreads();

    // ---- Block scan over 32 (warp,k) counts + ONE global atomic ----
    if (tid < 32) {
        int v = s_off[tid];
        int excl = v;
        #pragma unroll
        for (int sh = 1; sh < 32; sh <<= 1) {
            int n = __shfl_up_sync(0xffffffffu, excl, sh);
            if (tid >= sh) excl += n;
        }
        int incl = excl;
        excl -= v;                       // exclusive prefix
        if (tid == 31) s_base = atomicAdd(&g_cnt[b], incl);
        s_off[tid] = excl;
    }
    __syncthreads();

    // ---- Phase 2: write candidates ----
    const int base = s_base;
    #pragma unroll
    for (int k = 0; k < 4; k++) {
        const unsigned mask = um[k];
        const bool cand = (mask >> lane) & 1u;
        if (cand) {
            int pos = base + s_off[ty * 4 + k] + __popc(mask & ((1u << lane) - 1u));
            if (pos < MAXC) {
                float p = prob_from_d(dv[k]);
                g_cval[b][pos] = p;
                g_cidx[b][pos] = gy * WW + (bx0 + lane + k * 32);
                atomicAdd(&g_hist[b][__float_as_uint(p) >> 14], 1);
            }
        }
    }
}

// ---------------------------------------------------------------------------
// Kernel 2: per-batch threshold (histogram suffix scan) + collect + exact
// stable rank of survivors + output write. One block per batch.
// ---------------------------------------------------------------------------
#define COLLECT_CAP 1024

__global__ __launch_bounds__(256) void select_kernel(float* __restrict__ out) {
    __shared__ int   s_psum[256];
    __shared__ int   s_seg, s_above, s_cutbits, s_count;
    __shared__ float s_val[COLLECT_CAP];
    __shared__ int   s_idx[COLLECT_CAP];

    const int b = blockIdx.x;
    const int t = threadIdx.x;
    const int* __restrict__ hb = g_hist[b];

    // Coarse pass: per-thread sums over 256 contiguous bins (vectorized).
    int acc = 0;
    const int4* h4 = (const int4*)(hb + t * 256);
    #pragma unroll 8
    for (int j = 0; j < 64; j++) {
        int4 v = h4[j];
        acc += v.x + v.y + v.z + v.w;
    }
    s_psum[t] = acc;
    if (t == 0) s_count = 0;
    __syncthreads();

    if (t == 0) {
        int above = 0, seg = 0;
        for (int s = 255; s >= 0; s--) {
            if (above + s_psum[s] >= KK) { seg = s; break; }
            above += s_psum[s];
        }
        s_seg = seg; s_above = above;
    }
    __syncthreads();

    // Fine pass within the cut segment.
    const int seg = s_seg;
    s_psum[t] = hb[seg * 256 + t];
    __syncthreads();
    if (t == 0) {
        int above = s_above;
        int cut = seg * 256;
        for (int c = 255; c >= 0; c--) {
            if (above + s_psum[c] >= KK) { cut = seg * 256 + c; break; }
            above += s_psum[c];
        }
        s_cutbits = cut << 14;
    }
    __syncthreads();

    // Collect all candidates with bits >= cutbits (count in [100, ~100+binpop]).
    const unsigned cutbits = (unsigned)s_cutbits;
    const int n = min(g_cnt[b], MAXC);
    for (int i = t; i < n; i += 256) {
        float v = g_cval[b][i];
        if (__float_as_uint(v) >= cutbits) {
            int pos = atomicAdd(&s_count, 1);
            if (pos < COLLECT_CAP) { s_val[pos] = v; s_idx[pos] = g_cidx[b][i]; }
        }
    }
    __syncthreads();

    // Exact stable rank: value desc, index asc (matches lax.top_k tie-break).
    const int C = min(s_count, COLLECT_CAP);
    for (int e = t; e < C; e += 256) {
        const float v  = s_val[e];
        const int   id = s_idx[e];
        int rank = 0;
        for (int j = 0; j < C; j++) {
            float vj = s_val[j];
            rank += (vj > v) || (vj == v && s_idx[j] < id);
        }
        if (rank < KK) {
            int w = id % WW;
            int h = id / WW;
            float xc = (float)w * 4.0f + 1.5f;
            float yc = (float)h * 4.0f + 1.5f;
            float* o = out + ((size_t)b * KK + rank) * 5;
            o[0] = xc - 10.0f;
            o[1] = yc - 10.0f;
            o[2] = xc + 10.0f;
            o[3] = yc + 10.0f;
            o[4] = v;
        }
    }
}

// ---------------------------------------------------------------------------
extern "C" void kernel_launch(void* const* d_in, const int* in_sizes, int n_in,
                              void* d_out, int out_size) {
    const float* in = (const float*)d_in[0];
    float* out = (float*)d_out;

    // 0) reset counters + histogram
    {
        int n4 = (BB * NBINS) / 4;
        zero_kernel<<<(n4 + 255) / 256, 256>>>();
    }

    // 1) fused softmax-equivalent + NMS + candidate emit
    {
        dim3 block(32, 8);
        dim3 grid((WW + TILE_W - 1) / TILE_W, (HH + TILE_H - 1) / TILE_H, BB);
        detect_kernel<<<grid, block>>>(in);
    }

    // 2) per-batch top-100 + box write
    select_kernel<<<BB, 256>>>(out);
}

// round 3
// speedup vs baseline: 2.4984x; 1.5298x over previous
#include <cuda_runtime.h>
#include <math.h>
#include <stdint.h>

// FootAndBall ball-detection post-process.
//  in : [16, 2, 540, 960] fp32 logits
//  out: [16, 100, 5] fp32 (x1,y1,x2,y2,score), sorted by score desc (idx asc ties).
//
// Pipeline:
//  K0 zero     : reset 64 segment counters.
//  K1 detect   : d = x1-x0, 3x3 NMS on d (== NMS on softmax prob, monotone),
//                emit (d, idx) candidates into 4 segments/batch. NO per-candidate
//                global atomics (block-aggregated slot reservation only).
//  K2 select   : per-batch radix-select on order-preserving bits of d via
//                shared-mem histogram, exact (p, idx) rank of ~130 survivors.

#define BB   16
#define HH   540
#define WW   960
#define HWSZ (HH * WW)
#define KK   100
#define NSEG 4
#define SEGC 131072           // >= 136 rows * 960 = 130560 worst case

__device__ int   g_cnt[BB][NSEG];
__device__ float g_cd [BB][NSEG][SEGC];
__device__ int   g_ci [BB][NSEG][SEGC];

// ---------------------------------------------------------------------------
__global__ void zero_kernel() {
    int i = threadIdx.x;
    if (i < BB * NSEG) ((int*)g_cnt)[i] = 0;
}

// ---------------------------------------------------------------------------
// Exact softmax channel-1 prob from d = fl(x1-x0). Matches jax.nn.softmax:
// one exp arg is exactly 0, fl(x0-x1) == -d exactly. (Validated: rel_err 1e-12.)
// ---------------------------------------------------------------------------
__device__ __forceinline__ float prob_from_d(float d) {
#ifdef __FAST_MATH__
    double dd = (double)d;
    double p = (d >= 0.0f) ? (1.0 / (exp(-dd) + 1.0))
                           : (exp(dd) / (exp(dd) + 1.0));
    return (float)p;
#else
    if (d >= 0.0f) { float e0 = expf(-d); return 1.0f / (e0 + 1.0f); }
    else           { float e1 = expf(d);  return e1 / (1.0f + e1);  }
#endif
}

// Order-preserving bit flip for float compare as unsigned.
__device__ __forceinline__ unsigned fflip(float f) {
    unsigned u = __float_as_uint(f);
    return u ^ (((unsigned)((int)u >> 31)) | 0x80000000u);
}

// ---------------------------------------------------------------------------
// K1: fused d-map + 3x3 NMS + segmented candidate emit.
// ---------------------------------------------------------------------------
#define TILE_W 128
#define TILE_H 8

__global__ __launch_bounds__(256) void detect_kernel(const float* __restrict__ in) {
    __shared__ float sd[TILE_H + 2][TILE_W + 4];
    __shared__ int   s_off[32];
    __shared__ int   s_base;

    const int b   = blockIdx.z;
    const int seg = blockIdx.y & (NSEG - 1);
    const int bx0 = blockIdx.x * TILE_W;
    const int by0 = blockIdx.y * TILE_H;
    const float* __restrict__ p0 = in + (size_t)b * 2 * HWSZ;
    const float* __restrict__ p1 = p0 + HWSZ;

    const int lane = threadIdx.x;
    const int ty   = threadIdx.y;
    const int tid  = ty * 32 + lane;

    // Halo load (SAME padding = -inf).
    for (int i = tid; i < (TILE_H + 2) * (TILE_W + 2); i += 256) {
        int r  = i / (TILE_W + 2);
        int c  = i - r * (TILE_W + 2);
        int gx = bx0 + c - 1;
        int gy = by0 + r - 1;
        float d = -INFINITY;
        if (gx >= 0 && gx < WW && gy >= 0 && gy < HH) {
            int o = gy * WW + gx;
            d = p1[o] - p0[o];
        }
        sd[r][c] = d;
    }
    __syncthreads();

    const int gy = by0 + ty;

    // NMS decision, fully scalarized (no dynamic register-array indexing).
    float d0, d1, d2, d3;
    unsigned m0, m1, m2, m3;
#define NMS_STEP(K, DK, MK)                                                      \
    {                                                                            \
        const int cx = lane + (K) * 32;                                          \
        const int gx = bx0 + cx;                                                 \
        DK = sd[ty + 1][cx + 1];                                                 \
        float m = fmaxf(fmaxf(sd[ty][cx], sd[ty][cx + 1]), sd[ty][cx + 2]);      \
        m = fmaxf(m, fmaxf(sd[ty + 1][cx], sd[ty + 1][cx + 2]));                 \
        m = fmaxf(m, fmaxf(fmaxf(sd[ty + 2][cx], sd[ty + 2][cx + 1]),            \
                           sd[ty + 2][cx + 2]));                                 \
        bool cand = (gx < WW) && (gy < HH) && (DK >= m);                         \
        MK = __ballot_sync(0xffffffffu, cand);                                   \
    }
    NMS_STEP(0, d0, m0)
    NMS_STEP(1, d1, m1)
    NMS_STEP(2, d2, m2)
    NMS_STEP(3, d3, m3)
#undef NMS_STEP

    if (lane == 0) {
        s_off[ty * 4 + 0] = __popc(m0);
        s_off[ty * 4 + 1] = __popc(m1);
        s_off[ty * 4 + 2] = __popc(m2);
        s_off[ty * 4 + 3] = __popc(m3);
    }
    __syncthreads();

    // Block scan over the 32 (warp,k) counts + ONE global atomic per block.
    if (tid < 32) {
        int v = s_off[tid];
        int incl = v;
        #pragma unroll
        for (int sh = 1; sh < 32; sh <<= 1) {
            int n = __shfl_up_sync(0xffffffffu, incl, sh);
            if (tid >= sh) incl += n;
        }
        if (tid == 31) s_base = atomicAdd(&g_cnt[b][seg], incl);
        s_off[tid] = incl - v;           // exclusive prefix
    }
    __syncthreads();

    const int base = s_base;
    const unsigned lanemask = (1u << lane) - 1u;
#define EMIT(K, DK, MK)                                                          \
    if ((MK >> lane) & 1u) {                                                     \
        int pos = base + s_off[ty * 4 + (K)] + __popc(MK & lanemask);            \
        if (pos < SEGC) {                                                        \
            g_cd[b][seg][pos] = DK;                                              \
            g_ci[b][seg][pos] = gy * WW + (bx0 + lane + (K) * 32);               \
        }                                                                        \
    }
    EMIT(0, d0, m0)
    EMIT(1, d1, m1)
    EMIT(2, d2, m2)
    EMIT(3, d3, m3)
#undef EMIT
}

// ---------------------------------------------------------------------------
// K2: per-batch top-100. One block per batch, 512 threads.
//  pass 1: smem histogram of top-12 flip-bits -> cut bin so that >= 100 above.
//  pass 2: collect (d, idx) of all candidates with bin >= cut (~130 expected).
//  rank  : exact (p desc, idx asc) among survivors.
// ---------------------------------------------------------------------------
#define HB    4096
#define CAP   2048

__global__ __launch_bounds__(512) void select_kernel(float* __restrict__ out) {
    __shared__ int   s_hist[HB];          // reused as s_p (float) in rank phase
    __shared__ int   s_psum[512];
    __shared__ float s_d[CAP];
    __shared__ int   s_i[CAP];
    __shared__ int   s_cut, s_count;

    const int b = blockIdx.x;
    const int t = threadIdx.x;

    for (int i = t; i < HB; i += 512) s_hist[i] = 0;
    if (t == 0) s_count = 0;
    __syncthreads();

    int nseg[NSEG];
    #pragma unroll
    for (int s = 0; s < NSEG; s++) nseg[s] = min(g_cnt[b][s], SEGC);

    // Pass 1: histogram of flip(d) >> 20.
    #pragma unroll
    for (int s = 0; s < NSEG; s++) {
        const float* __restrict__ cd = g_cd[b][s];
        for (int i = t; i < nseg[s]; i += 512)
            atomicAdd(&s_hist[fflip(cd[i]) >> 20], 1);
    }
    __syncthreads();

    // Suffix threshold: smallest bin c with count(bin >= c) >= KK.
    {
        int acc = 0;
        #pragma unroll
        for (int j = 0; j < 8; j++) acc += s_hist[t * 8 + j];
        s_psum[t] = acc;
    }
    __syncthreads();
    if (t == 0) {
        int above = 0, segi = 0;
        for (int s = 511; s >= 0; s--) {
            if (above + s_psum[s] >= KK) { segi = s; break; }
            above += s_psum[s];
        }
        int cut = segi * 8;
        for (int c = segi * 8 + 7; c >= segi * 8; c--) {
            if (above + s_hist[c] >= KK) { cut = c; break; }
            above += s_hist[c];
        }
        s_cut = cut;
    }
    __syncthreads();

    // Pass 2: collect survivors (bin >= cut).
    const unsigned cutbits = ((unsigned)s_cut) << 20;
    #pragma unroll
    for (int s = 0; s < NSEG; s++) {
        const float* __restrict__ cd = g_cd[b][s];
        const int*   __restrict__ ci = g_ci[b][s];
        for (int i = t; i < nseg[s]; i += 512) {
            float d = cd[i];
            if (fflip(d) >= cutbits) {
                int pos = atomicAdd(&s_count, 1);
                if (pos < CAP) { s_d[pos] = d; s_i[pos] = ci[i]; }
            }
        }
    }
    __syncthreads();

    const int C = min(s_count, CAP);

    // Exact p for survivors only (reuse s_hist storage as float buffer).
    float* s_p = (float*)s_hist;
    for (int e = t; e < C; e += 512) s_p[e] = prob_from_d(s_d[e]);
    __syncthreads();

    // Exact stable rank: p desc, idx asc (lax.top_k tie-break).
    for (int e = t; e < C; e += 512) {
        const float v  = s_p[e];
        const int   id = s_i[e];
        int rank = 0;
        for (int j = 0; j < C; j++) {
            float vj = s_p[j];
            rank += (vj > v) || (vj == v && s_i[j] < id);
        }
        if (rank < KK) {
            int w = id % WW;
            int h = id / WW;
            float xc = (float)w * 4.0f + 1.5f;
            float yc = (float)h * 4.0f + 1.5f;
            float* o = out + ((size_t)b * KK + rank) * 5;
            o[0] = xc - 10.0f;
            o[1] = yc - 10.0f;
            o[2] = xc + 10.0f;
            o[3] = yc + 10.0f;
            o[4] = v;
        }
    }
}

// ---------------------------------------------------------------------------
extern "C" void kernel_launch(void* const* d_in, const int* in_sizes, int n_in,
                              void* d_out, int out_size) {
    const float* in = (const float*)d_in[0];
    float* out = (float*)d_out;

    zero_kernel<<<1, 64>>>();

    dim3 block(32, 8);
    dim3 grid((WW + TILE_W - 1) / TILE_W, (HH + TILE_H - 1) / TILE_H, BB);
    detect_kernel<<<grid, block>>>(in);

    select_kernel<<<BB, 512>>>(out);
}

// round 4
// speedup vs baseline: 2.7792x; 1.1124x over previous
#include <cuda_runtime.h>
#include <math.h>
#include <stdint.h>

// FootAndBall ball-detection post-process.
//  in : [16, 2, 540, 960] fp32 logits
//  out: [16, 100, 5] fp32 (x1,y1,x2,y2,score), score desc (idx asc on ties).
//
//  K1 detect : d = x1-x0 (NMS on d == NMS on softmax prob, monotone).
//              Register-streaming 3x3 NMS: warp owns 30 columns, rows streamed
//              with shfl-based horizontal max + rolling vertical max.
//              Candidates staged in per-warp smem queues, flushed coalesced.
//  K2 select : per-batch radix threshold on order-flipped d bits (smem hist),
//              exact (p desc, idx asc) rank of ~150 survivors, box write.
//              Also resets counters for the next graph replay (no zero kernel;
//              __device__ globals start zero-initialized).

#define BB   16
#define HH   540
#define WW   960
#define HWSZ (HH * WW)
#define KK   100

#define CH    36                  // rows per chunk; 540 = 15 * 36
#define NCH   15
#define WARPS 16                  // warps per block; block covers 16*30=480 cols
#define QCAP  160                 // per-warp smem queue entries
#define SEGC  (CH * WW)           // worst-case candidates per (batch, chunk)

__device__ int    g_cnt [BB][NCH];          // zero-initialized at module load
__device__ float2 g_cand[BB][NCH][SEGC];    // (d, idx-bits)

// ---------------------------------------------------------------------------
// Exact softmax channel-1 prob from d = fl(x1-x0). Matches jax.nn.softmax:
// one exp arg is exactly 0, and fl(x0-x1) == -d exactly. (rel_err ~1e-12.)
// ---------------------------------------------------------------------------
__device__ __forceinline__ float prob_from_d(float d) {
#ifdef __FAST_MATH__
    double dd = (double)d;
    double p = (d >= 0.0f) ? (1.0 / (exp(-dd) + 1.0))
                           : (exp(dd) / (exp(dd) + 1.0));
    return (float)p;
#else
    if (d >= 0.0f) { float e0 = expf(-d); return 1.0f / (e0 + 1.0f); }
    else           { float e1 = expf(d);  return e1 / (1.0f + e1);  }
#endif
}

// Order-preserving bit flip: float compare == unsigned compare after flip.
__device__ __forceinline__ unsigned fflip(float f) {
    unsigned u = __float_as_uint(f);
    return u ^ (((unsigned)((int)u >> 31)) | 0x80000000u);
}

// ---------------------------------------------------------------------------
// K1: register-streaming NMS + queued candidate emit.
// Grid (2, 15, 16), block 512 (= 16 warps of 30 output cols each).
// ---------------------------------------------------------------------------
__device__ __forceinline__ void flush_queue(float2* __restrict__ sq, int& qcnt,
                                            int lane, int* __restrict__ ctr,
                                            float2* __restrict__ gseg) {
    if (qcnt == 0) return;                       // warp-uniform
    int base = 0;
    if (lane == 0) base = atomicAdd(ctr, qcnt);
    base = __shfl_sync(0xffffffffu, base, 0);
    for (int i = lane; i < qcnt; i += 32)        // coalesced 256B bursts
        gseg[base + i] = sq[i];
    qcnt = 0;
}

__global__ __launch_bounds__(512) void detect_kernel(const float* __restrict__ in) {
    __shared__ float2 squeue[WARPS][QCAP];       // 20 KB

    const int b     = blockIdx.z;
    const int chunk = blockIdx.y;
    const int w     = threadIdx.x >> 5;
    const int lane  = threadIdx.x & 31;
    const int col   = blockIdx.x * (WARPS * 30) + w * 30 + lane - 1;
    const bool colok = (col >= 0) && (col < WW);
    const int r0    = chunk * CH;

    const float* __restrict__ p0 = in + (size_t)b * 2 * HWSZ;
    const float* __restrict__ p1 = p0 + HWSZ;

    int*    __restrict__ ctr  = &g_cnt[b][chunk];
    float2* __restrict__ gseg = g_cand[b][chunk];
    float2* __restrict__ sq   = squeue[w];
    int qcnt = 0;

    // d at (row r, this lane's col); OOB (SAME padding) = -inf.
    #define LOADROW(R) \
        ((colok && (unsigned)(R) < (unsigned)HH) \
            ? (__ldg(p1 + (R) * WW + col) - __ldg(p0 + (R) * WW + col)) \
            : -INFINITY)
    // horizontal 3-max via neighbor shuffles (valid for lanes 1..30)
    #define H3MAX(D, OUT) { \
        float _l = __shfl_up_sync(0xffffffffu, (D), 1); \
        float _r = __shfl_down_sync(0xffffffffu, (D), 1); \
        OUT = fmaxf(fmaxf(_l, (D)), _r); }

    float d_0, hm_m1, hm_0;
    { float d_m1 = LOADROW(r0 - 1); H3MAX(d_m1, hm_m1); }
    d_0 = LOADROW(r0);  H3MAX(d_0, hm_0);

    const bool lane_ok = (lane >= 1) && (lane <= 30) && (col < WW);
    const unsigned below = (1u << lane) - 1u;

    #pragma unroll 4
    for (int r = r0; r < r0 + CH; r++) {
        float d_p1 = LOADROW(r + 1);
        float hm_p1; H3MAX(d_p1, hm_p1);

        float m = fmaxf(fmaxf(hm_m1, hm_0), hm_p1);     // 3x3 max incl. center
        bool cand = lane_ok && (d_0 >= m);              // d == max

        unsigned mask = __ballot_sync(0xffffffffu, cand);
        int nc = __popc(mask);
        if (qcnt + nc > QCAP) flush_queue(sq, qcnt, lane, ctr, gseg);
        if (cand) {
            int pos = qcnt + __popc(mask & below);
            sq[pos] = make_float2(d_0, __int_as_float(r * WW + col));
        }
        qcnt += nc;

        hm_m1 = hm_0; hm_0 = hm_p1; d_0 = d_p1;
    }
    flush_queue(sq, qcnt, lane, ctr, gseg);
    #undef LOADROW
    #undef H3MAX
}

// ---------------------------------------------------------------------------
// K2: per-batch top-100. One block per batch, 512 threads.
// ---------------------------------------------------------------------------
#define HB  4096
#define CAP 2048

__global__ __launch_bounds__(512) void select_kernel(float* __restrict__ out) {
    __shared__ int   s_hist[HB];        // reused as float p[] in rank phase
    __shared__ int   s_psum[512];
    __shared__ int   s_cntl[NCH];
    __shared__ float s_d[CAP];
    __shared__ int   s_i[CAP];
    __shared__ int   s_cut, s_count;

    const int b = blockIdx.x;
    const int t = threadIdx.x;

    for (int i = t; i < HB; i += 512) s_hist[i] = 0;
    if (t < NCH) s_cntl[t] = min(g_cnt[b][t], SEGC);
    if (t == 0) s_count = 0;
    __syncthreads();

    // Reset counters for the next replay (all threads already staged them).
    if (t < NCH) g_cnt[b][t] = 0;

    // Pass 1: histogram of top-12 order-flipped bits of d.
    for (int s = 0; s < NCH; s++) {
        const float2* __restrict__ cd = g_cand[b][s];
        const int n = s_cntl[s];
        for (int i = t; i < n; i += 512)
            atomicAdd(&s_hist[fflip(cd[i].x) >> 20], 1);
    }
    __syncthreads();

    // Threshold: smallest bin c with count(bin >= c) >= KK.
    {
        int acc = 0;
        #pragma unroll
        for (int j = 0; j < 8; j++) acc += s_hist[t * 8 + j];
        s_psum[t] = acc;
    }
    __syncthreads();
    if (t == 0) {
        int above = 0, segi = 0;
        for (int s = 511; s >= 0; s--) {
            if (above + s_psum[s] >= KK) { segi = s; break; }
            above += s_psum[s];
        }
        int cut = segi * 8;
        for (int c = segi * 8 + 7; c >= segi * 8; c--) {
            if (above + s_hist[c] >= KK) { cut = c; break; }
            above += s_hist[c];
        }
        s_cut = cut;
    }
    __syncthreads();

    // Pass 2: collect survivors (bin >= cut); expected ~100-300, L2-resident.
    const unsigned cutbits = ((unsigned)s_cut) << 20;
    for (int s = 0; s < NCH; s++) {
        const float2* __restrict__ cd = g_cand[b][s];
        const int n = s_cntl[s];
        for (int i = t; i < n; i += 512) {
            float2 v = cd[i];
            if (fflip(v.x) >= cutbits) {
                int pos = atomicAdd(&s_count, 1);
                if (pos < CAP) { s_d[pos] = v.x; s_i[pos] = __float_as_int(v.y); }
            }
        }
    }
    __syncthreads();

    const int C = min(s_count, CAP);

    // Exact p for survivors only (reuse s_hist as float storage).
    float* s_p = (float*)s_hist;
    for (int e = t; e < C; e += 512) s_p[e] = prob_from_d(s_d[e]);
    __syncthreads();

    // Exact stable rank: p desc, idx asc (lax.top_k tie-break).
    for (int e = t; e < C; e += 512) {
        const float v  = s_p[e];
        const int   id = s_i[e];
        int rank = 0;
        for (int j = 0; j < C; j++) {
            float vj = s_p[j];
            rank += (vj > v) || (vj == v && s_i[j] < id);
        }
        if (rank < KK) {
            int ww = id % WW;
            int hh = id / WW;
            float xc = (float)ww * 4.0f + 1.5f;
            float yc = (float)hh * 4.0f + 1.5f;
            float* o = out + ((size_t)b * KK + rank) * 5;
            o[0] = xc - 10.0f;
            o[1] = yc - 10.0f;
            o[2] = xc + 10.0f;
            o[3] = yc + 10.0f;
            o[4] = v;
        }
    }
}

// ---------------------------------------------------------------------------
extern "C" void kernel_launch(void* const* d_in, const int* in_sizes, int n_in,
                              void* d_out, int out_size) {
    const float* in = (const float*)d_in[0];
    float* out = (float*)d_out;

    dim3 grid(WW / (WARPS * 30), NCH, BB);   // (2, 15, 16)
    detect_kernel<<<grid, 512>>>(in);

    select_kernel<<<BB, 512>>>(out);
}

// round 5
// speedup vs baseline: 3.3471x; 1.2043x over previous
#include <cuda_runtime.h>
#include <math.h>
#include <stdint.h>

// FootAndBall ball-detection post-process.
//  in : [16, 2, 540, 960] fp32 logits
//  out: [16, 100, 5] fp32 (x1,y1,x2,y2,score), score desc (idx asc on ties).
//
//  K1 detect : d = x1-x0 (NMS on d == NMS on softmax prob, monotone).
//              Register-streaming 3x3 NMS; per-warp smem candidate queues;
//              FUSED per-block smem histogram of order-flipped d bits,
//              merged into the global per-batch histogram (nonzero REDs).
//  K2 cut    : per-batch suffix scan of the 4096-bin hist -> cut bits.
//  K3 collect: per-(batch,chunk) blocks filter candidates >= cut into small
//              per-chunk survivor lists (~20 each).
//  K4 rank   : per-batch exact (p desc, idx asc) rank of ~150-300 survivors,
//              box write, and state reset for the next graph replay.
// __device__ globals are zero-initialized at load; K4 restores zeros.

#define BB   16
#define HH   540
#define WW   960
#define HWSZ (HH * WW)
#define KK   100

#define CH    36                  // rows per chunk; 540 = 15 * 36
#define NCH   15
#define WARPS 16                  // detect warps/block; covers 16*30=480 cols
#define QCAP  160                 // per-warp smem queue entries
#define SEGC  (CH * WW)           // worst-case candidates per (batch, chunk)
#define HB    4096                // histogram bins (top 12 flipped bits)
#define SVCAP 1024                // per-(batch,chunk) survivor capacity
#define TOTC  4096                // per-batch gathered survivor cap

__device__ int    g_cnt [BB][NCH];
__device__ float2 g_cand[BB][NCH][SEGC];
__device__ int    g_hist[BB][HB];
__device__ unsigned g_cut[BB];
__device__ int    g_svc [BB][NCH];
__device__ float2 g_sv  [BB][NCH][SVCAP];

// ---------------------------------------------------------------------------
// Exact softmax channel-1 prob from d = fl(x1-x0). Matches jax.nn.softmax:
// one exp arg is exactly 0 and fl(x0-x1) == -d exactly. (rel_err ~1e-12.)
// ---------------------------------------------------------------------------
__device__ __forceinline__ float prob_from_d(float d) {
#ifdef __FAST_MATH__
    double dd = (double)d;
    double p = (d >= 0.0f) ? (1.0 / (exp(-dd) + 1.0))
                           : (exp(dd) / (exp(dd) + 1.0));
    return (float)p;
#else
    if (d >= 0.0f) { float e0 = expf(-d); return 1.0f / (e0 + 1.0f); }
    else           { float e1 = expf(d);  return e1 / (1.0f + e1);  }
#endif
}

// Order-preserving bit flip: float compare == unsigned compare after flip.
__device__ __forceinline__ unsigned fflip(float f) {
    unsigned u = __float_as_uint(f);
    return u ^ (((unsigned)((int)u >> 31)) | 0x80000000u);
}

// ---------------------------------------------------------------------------
// K1: register-streaming NMS + queued emit + fused histogram.
// Grid (2, 15, 16), block 512 (16 warps x 30 output cols).
// ---------------------------------------------------------------------------
__device__ __forceinline__ void flush_queue(float2* __restrict__ sq, int& qcnt,
                                            int lane, int* __restrict__ ctr,
                                            float2* __restrict__ gseg) {
    if (qcnt == 0) return;                       // warp-uniform
    int base = 0;
    if (lane == 0) base = atomicAdd(ctr, qcnt);
    base = __shfl_sync(0xffffffffu, base, 0);
    for (int i = lane; i < qcnt; i += 32)        // coalesced bursts
        gseg[base + i] = sq[i];
    qcnt = 0;
}

__global__ __launch_bounds__(512) void detect_kernel(const float* __restrict__ in) {
    __shared__ float2 squeue[WARPS][QCAP];       // 20 KB
    __shared__ int    shist[HB];                 // 16 KB

    const int b     = blockIdx.z;
    const int chunk = blockIdx.y;
    const int w     = threadIdx.x >> 5;
    const int lane  = threadIdx.x & 31;
    const int tid   = threadIdx.x;
    const int col   = blockIdx.x * (WARPS * 30) + w * 30 + lane - 1;
    const bool colok = (col >= 0) && (col < WW);
    const int r0    = chunk * CH;

    #pragma unroll
    for (int i = tid; i < HB; i += 512) shist[i] = 0;
    __syncthreads();

    const float* __restrict__ p0 = in + (size_t)b * 2 * HWSZ;
    const float* __restrict__ p1 = p0 + HWSZ;

    int*    __restrict__ ctr  = &g_cnt[b][chunk];
    float2* __restrict__ gseg = g_cand[b][chunk];
    float2* __restrict__ sq   = squeue[w];
    int qcnt = 0;

    #define LOADROW(R) \
        ((colok && (unsigned)(R) < (unsigned)HH) \
            ? (__ldg(p1 + (R) * WW + col) - __ldg(p0 + (R) * WW + col)) \
            : -INFINITY)
    #define H3MAX(D, OUT) { \
        float _l = __shfl_up_sync(0xffffffffu, (D), 1); \
        float _r = __shfl_down_sync(0xffffffffu, (D), 1); \
        OUT = fmaxf(fmaxf(_l, (D)), _r); }

    float d_0, hm_m1, hm_0;
    { float d_m1 = LOADROW(r0 - 1); H3MAX(d_m1, hm_m1); }
    d_0 = LOADROW(r0);  H3MAX(d_0, hm_0);

    const bool lane_ok = (lane >= 1) && (lane <= 30) && (col < WW);
    const unsigned below = (1u << lane) - 1u;

    #pragma unroll 4
    for (int r = r0; r < r0 + CH; r++) {
        float d_p1 = LOADROW(r + 1);
        float hm_p1; H3MAX(d_p1, hm_p1);

        float m = fmaxf(fmaxf(hm_m1, hm_0), hm_p1);
        bool cand = lane_ok && (d_0 >= m);

        unsigned mask = __ballot_sync(0xffffffffu, cand);
        int nc = __popc(mask);
        if (qcnt + nc > QCAP) flush_queue(sq, qcnt, lane, ctr, gseg);
        if (cand) {
            int pos = qcnt + __popc(mask & below);
            sq[pos] = make_float2(d_0, __int_as_float(r * WW + col));
            atomicAdd(&shist[fflip(d_0) >> 20], 1);     // spread-address ATOMS
        }
        qcnt += nc;

        hm_m1 = hm_0; hm_0 = hm_p1; d_0 = d_p1;
    }
    flush_queue(sq, qcnt, lane, ctr, gseg);
    #undef LOADROW
    #undef H3MAX

    __syncthreads();
    // Merge nonzero bins into the global per-batch histogram (RED, no return).
    #pragma unroll
    for (int i = tid; i < HB; i += 512) {
        int v = shist[i];
        if (v) atomicAdd(&g_hist[b][i], v);
    }
}

// ---------------------------------------------------------------------------
// K2: per-batch cut = smallest bin c with count(bin >= c) >= KK.
// ---------------------------------------------------------------------------
__global__ __launch_bounds__(512) void cut_kernel() {
    __shared__ int s_psum[512];
    const int b = blockIdx.x;
    const int t = threadIdx.x;
    const int* __restrict__ hb = g_hist[b];

    int acc = 0;
    #pragma unroll
    for (int j = 0; j < 8; j++) acc += hb[t * 8 + j];
    s_psum[t] = acc;
    __syncthreads();

    if (t == 0) {
        int above = 0, segi = 0;
        for (int s = 511; s >= 0; s--) {
            if (above + s_psum[s] >= KK) { segi = s; break; }
            above += s_psum[s];
        }
        int cut = segi * 8;
        for (int c = segi * 8 + 7; c >= segi * 8; c--) {
            if (above + hb[c] >= KK) { cut = c; break; }
            above += hb[c];
        }
        g_cut[b] = ((unsigned)cut) << 20;
    }
}

// ---------------------------------------------------------------------------
// K3: per-(batch,chunk) filter of candidates >= cut into survivor lists.
// Grid (NCH, BB), block 256.
// ---------------------------------------------------------------------------
__global__ __launch_bounds__(256) void collect_kernel() {
    const int ch = blockIdx.x;
    const int b  = blockIdx.y;
    const int t  = threadIdx.x;
    const int n  = min(g_cnt[b][ch], SEGC);
    const unsigned cut = g_cut[b];
    const float2* __restrict__ cd = g_cand[b][ch];

    for (int i = t; i < n; i += 256) {
        float2 v = cd[i];
        if (fflip(v.x) >= cut) {
            int pos = atomicAdd(&g_svc[b][ch], 1);
            if (pos < SVCAP) g_sv[b][ch][pos] = v;
        }
    }
}

// ---------------------------------------------------------------------------
// K4: per-batch gather + exact stable rank + box write + state reset.
// Grid BB, block 512.
// ---------------------------------------------------------------------------
__global__ __launch_bounds__(512) void rank_kernel(float* __restrict__ out) {
    __shared__ float s_p[TOTC];         // survivor probs (d overwritten by p)
    __shared__ int   s_i[TOTC];
    __shared__ int   s_off[NCH + 1];

    const int b = blockIdx.x;
    const int t = threadIdx.x;

    if (t == 0) {
        int off = 0;
        for (int ch = 0; ch < NCH; ch++) {
            s_off[ch] = off;
            off += min(g_svc[b][ch], SVCAP);
        }
        s_off[NCH] = off;
    }
    __syncthreads();

    // Gather survivors; compute exact p immediately.
    for (int ch = 0; ch < NCH; ch++) {
        const int o = s_off[ch];
        const int nn = s_off[ch + 1] - o;
        const float2* __restrict__ sv = g_sv[b][ch];
        for (int i = t; i < nn; i += 512) {
            if (o + i < TOTC) {
                float2 v = sv[i];
                s_p[o + i] = prob_from_d(v.x);
                s_i[o + i] = __float_as_int(v.y);
            }
        }
    }
    __syncthreads();

    const int C = min(s_off[NCH], TOTC);

    // Exact stable rank: p desc, idx asc (lax.top_k tie-break).
    for (int e = t; e < C; e += 512) {
        const float v  = s_p[e];
        const int   id = s_i[e];
        int rank = 0;
        for (int j = 0; j < C; j++) {
            float vj = s_p[j];
            rank += (vj > v) || (vj == v && s_i[j] < id);
        }
        if (rank < KK) {
            int ww = id % WW;
            int hh = id / WW;
            float xc = (float)ww * 4.0f + 1.5f;
            float yc = (float)hh * 4.0f + 1.5f;
            float* o = out + ((size_t)b * KK + rank) * 5;
            o[0] = xc - 10.0f;
            o[1] = yc - 10.0f;
            o[2] = xc + 10.0f;
            o[3] = yc + 10.0f;
            o[4] = v;
        }
    }

    // Reset all per-batch state for the next graph replay.
    for (int i = t; i < HB; i += 512) g_hist[b][i] = 0;
    if (t < NCH) { g_cnt[b][t] = 0; g_svc[b][t] = 0; }
}

// ---------------------------------------------------------------------------
extern "C" void kernel_launch(void* const* d_in, const int* in_sizes, int n_in,
                              void* d_out, int out_size) {
    const float* in = (const float*)d_in[0];
    float* out = (float*)d_out;

    dim3 dgrid(WW / (WARPS * 30), NCH, BB);      // (2, 15, 16)
    detect_kernel<<<dgrid, 512>>>(in);

    cut_kernel<<<BB, 512>>>();

    dim3 cgrid(NCH, BB);                          // (15, 16)
    collect_kernel<<<cgrid, 256>>>();

    rank_kernel<<<BB, 512>>>(out);
}